// round 3
// baseline (speedup 1.0000x reference)
#include <cuda_runtime.h>
#include <math.h>

#define B_   2
#define T_   2048
#define BT   4096
#define DIM  512
#define H_   8
#define DH   64
#define NH   8
#define NB   32
#define NCH  256      // NH*NB chunks per bh
#define BH   16
#define NHT  16384    // NH*T
#define KC   704      // padded conv K (229*3=687 -> 704)
#define FF   2048

typedef unsigned long long u64;

// ---- packed f32x2 primitives (lane-wise .rn, bit-identical to scalar) ------
__device__ __forceinline__ u64 pk2(float lo, float hi) {
    u64 r; asm("mov.b64 %0, {%1,%2};" : "=l"(r) : "f"(lo), "f"(hi)); return r;
}
__device__ __forceinline__ float2 upk2(u64 v) {
    float2 f; asm("mov.b64 {%0,%1}, %2;" : "=f"(f.x), "=f"(f.y) : "l"(v)); return f;
}
__device__ __forceinline__ u64 mul2(u64 a, u64 b) {
    u64 r; asm("mul.rn.f32x2 %0,%1,%2;" : "=l"(r) : "l"(a), "l"(b)); return r;
}
__device__ __forceinline__ u64 add2(u64 a, u64 b) {
    u64 r; asm("add.rn.f32x2 %0,%1,%2;" : "=l"(r) : "l"(a), "l"(b)); return r;
}
__device__ __forceinline__ u64 fma2(u64 a, u64 b, u64 c) {
    u64 r; asm("fma.rn.f32x2 %0,%1,%2,%3;" : "=l"(r) : "l"(a), "l"(b), "l"(c)); return r;
}
#define NEG1P 0xBF800000BF800000ULL
// packed Kahan: y=p-c; t=s+y; c=(t-s)-y; s=t  (each step single-rounded)
#define KAHAN2(s, c, p) { u64 y_ = fma2((c), NEG1P, (p)); u64 t_ = add2((s), y_); \
                          u64 u_ = fma2((s), NEG1P, t_); (c) = fma2(y_, NEG1P, u_); (s) = t_; }
// scalar Kahan
#define KAHAN(s, c, p) { float y_ = (p) - (c); float t_ = (s) + y_; (c) = (t_ - (s)) - y_; (s) = t_; }

// ------------------------- scratch (static device) -------------------------
__device__ float g_x1[BT*DIM];
__device__ float g_x2[BT*DIM];
__device__ float g_tmp[BT*DIM];
__device__ float g_qk[BT*DIM];
__device__ float g_v [BT*DIM];
__device__ float g_at[BT*DIM];
__device__ float g_ffb[BT*FF];
__device__ float g_im[BT*KC];
__device__ float g_wT[KC*DIM];
__device__ int   g_bk[BH*NHT];
__device__ int   g_st[BH*NHT];
__device__ float g_o [BH*NHT*DH];
__device__ float g_lg[BH*NHT];

// ------------------------- SGEMM: C = act(A@B + bias) + resid --------------
// Packed-f32x2 Kahan accumulation. A: MxK row-major, B: KxN row-major.
// BM=128, BN=64, BK=16, 256 threads. act: 0 none, 1 relu, 2 gelu(exact).
__global__ __launch_bounds__(256) void sgemm(
    const float* __restrict__ A, const float* __restrict__ Bm,
    const float* __restrict__ bias, const float* __restrict__ resid,
    float* __restrict__ C, int M, int N, int K, int act, int heads)
{
    __shared__ float As[16][132];
    __shared__ float Bs[16][64];
    const int tid = threadIdx.x;
    const int tx = tid & 15, ty = tid >> 4;
    const int m0 = blockIdx.y * 128, n0 = blockIdx.x * 64;

    u64 acc[8][2], cmp[8][2];
    #pragma unroll
    for (int i = 0; i < 8; i++) {
        acc[i][0] = 0ull; acc[i][1] = 0ull;
        cmp[i][0] = 0ull; cmp[i][1] = 0ull;
    }

    const int arow0 = tid >> 2, ac4 = (tid & 3) * 4;
    const int brow = tid >> 4, bc4 = (tid & 15) * 4;
    const int bcol = n0 + bc4;

    for (int k0 = 0; k0 < K; k0 += 16) {
        #pragma unroll
        for (int s = 0; s < 2; s++) {
            int row = arow0 + s * 64;
            float4 a = *(const float4*)(A + (size_t)(m0 + row) * K + k0 + ac4);
            As[ac4 + 0][row] = a.x; As[ac4 + 1][row] = a.y;
            As[ac4 + 2][row] = a.z; As[ac4 + 3][row] = a.w;
        }
        float4 bv;
        if (bcol < N) bv = *(const float4*)(Bm + (size_t)(k0 + brow) * N + bcol);
        else          bv = make_float4(0.f, 0.f, 0.f, 0.f);
        *(float4*)(&Bs[brow][bc4]) = bv;
        __syncthreads();
        #pragma unroll
        for (int k = 0; k < 16; k++) {
            float4 a0 = *(const float4*)(&As[k][ty * 8]);
            float4 a1 = *(const float4*)(&As[k][ty * 8 + 4]);
            float4 bb = *(const float4*)(&Bs[k][tx * 4]);
            u64 bw0 = pk2(bb.x, bb.y), bw1 = pk2(bb.z, bb.w);
            float av[8] = {a0.x, a0.y, a0.z, a0.w, a1.x, a1.y, a1.z, a1.w};
            #pragma unroll
            for (int i = 0; i < 8; i++) {
                u64 ai = pk2(av[i], av[i]);
                u64 p0 = mul2(ai, bw0); KAHAN2(acc[i][0], cmp[i][0], p0);
                u64 p1 = mul2(ai, bw1); KAHAN2(acc[i][1], cmp[i][1], p1);
            }
        }
        __syncthreads();
    }

    #pragma unroll
    for (int i = 0; i < 8; i++) {
        int row = m0 + ty * 8 + i;
        #pragma unroll
        for (int jj = 0; jj < 2; jj++) {
            float2 s = upk2(acc[i][jj]);
            float2 cc = upk2(cmp[i][jj]);
            float vv[2] = {s.x + cc.x, s.y + cc.y};
            #pragma unroll
            for (int q = 0; q < 2; q++) {
                int col = n0 + tx * 4 + jj * 2 + q;
                if (col >= N) continue;
                float v = vv[q];
                if (bias) v += bias[col];
                if (act == 1) v = fmaxf(v, 0.f);
                else if (act == 2) v = 0.5f * v * (1.f + erff(v * 0.70710678118654752f));
                if (resid) v += resid[(size_t)row * N + col];
                if (heads) {
                    int b = row >> 11, t = row & 2047;
                    int h = col >> 6, d = col & 63;
                    C[((((size_t)b * H_ + h) * T_ + t) << 6) + d] = v;
                } else {
                    C[(size_t)row * N + col] = v;
                }
            }
        }
    }
}

// ------------------------- LayerNorm (row of 512) ---------------------------
__global__ __launch_bounds__(256) void ln_kernel(
    const float* __restrict__ x, const float* __restrict__ g,
    const float* __restrict__ bb, float* __restrict__ y)
{
    __shared__ float sh[8];
    int row = blockIdx.x, tid = threadIdx.x;
    const float* xr = x + (size_t)row * DIM;
    float v0 = xr[tid], v1 = xr[tid + 256];
    float s = v0 + v1;
    #pragma unroll
    for (int o = 16; o; o >>= 1) s += __shfl_down_sync(0xffffffffu, s, o);
    if ((tid & 31) == 0) sh[tid >> 5] = s;
    __syncthreads();
    if (tid < 32) {
        float t = (tid < 8) ? sh[tid] : 0.f;
        #pragma unroll
        for (int o = 4; o; o >>= 1) t += __shfl_down_sync(0xffffffffu, t, o);
        if (tid == 0) sh[0] = t;
    }
    __syncthreads();
    float mean = sh[0] * (1.f / DIM);
    __syncthreads();
    float d0 = v0 - mean, d1 = v1 - mean;
    float s2 = d0 * d0 + d1 * d1;
    #pragma unroll
    for (int o = 16; o; o >>= 1) s2 += __shfl_down_sync(0xffffffffu, s2, o);
    if ((tid & 31) == 0) sh[tid >> 5] = s2;
    __syncthreads();
    if (tid < 32) {
        float t = (tid < 8) ? sh[tid] : 0.f;
        #pragma unroll
        for (int o = 4; o; o >>= 1) t += __shfl_down_sync(0xffffffffu, t, o);
        if (tid == 0) sh[0] = t;
    }
    __syncthreads();
    float inv = 1.f / sqrtf(sh[0] * (1.f / DIM) + 1e-5f);
    float* yr = y + (size_t)row * DIM;
    yr[tid]       = d0 * inv * g[tid]       + bb[tid];
    yr[tid + 256] = d1 * inv * g[tid + 256] + bb[tid + 256];
}

// ------------------------- LSH hashing --------------------------------------
#define TCH 16
__global__ __launch_bounds__(128) void hash_kernel(
    const float* __restrict__ qk, const float* __restrict__ rot, int* __restrict__ bkt)
{
    __shared__ float q[4][DH];
    int blk = blockIdx.x;
    int bh = blk / (T_ / TCH);
    int t0 = (blk % (T_ / TCH)) * TCH;
    int tid = threadIdx.x;
    int h = tid >> 4, j = tid & 15;
    float rv[64];
    #pragma unroll
    for (int f = 0; f < 64; f++) rv[f] = rot[f * 128 + h * 16 + j];

    for (int tg = 0; tg < TCH; tg += 4) {
        __syncthreads();
        for (int idx = tid; idx < 4 * DH; idx += 128) {
            int r = idx >> 6, d = idx & 63;
            q[r][d] = qk[((size_t)bh * T_ + t0 + tg + r) * DH + d];
        }
        __syncthreads();
        float a0 = 0.f, a1 = 0.f, a2 = 0.f, a3 = 0.f;
        float c0 = 0.f, c1 = 0.f, c2 = 0.f, c3 = 0.f;
        #pragma unroll
        for (int f = 0; f < 64; f++) {
            float r = rv[f];
            float p0 = q[0][f] * r; KAHAN(a0, c0, p0);
            float p1 = q[1][f] * r; KAHAN(a1, c1, p1);
            float p2 = q[2][f] * r; KAHAN(a2, c2, p2);
            float p3 = q[3][f] * r; KAHAN(a3, c3, p3);
        }
        float vals[4] = {a0 + c0, a1 + c1, a2 + c2, a3 + c3};
        #pragma unroll
        for (int r = 0; r < 4; r++) {
            float v = vals[r]; int idx = j;
            float nv = -v;
            if (nv > v) { v = nv; idx = j + 16; }   // ties keep +r (smaller index)
            #pragma unroll
            for (int o = 8; o; o >>= 1) {
                float ov = __shfl_down_sync(0xffffffffu, v, o, 16);
                int   oi = __shfl_down_sync(0xffffffffu, idx, o, 16);
                if (ov > v || (ov == v && oi < idx)) { v = ov; idx = oi; }
            }
            if (j == 0) bkt[(size_t)bh * NHT + h * T_ + t0 + tg + r] = idx + h * NB;
        }
    }
}

// ------------------------- stable counting sort by (bucket, pos) ------------
__global__ __launch_bounds__(256) void sort_kernel(
    const int* __restrict__ bkt, int* __restrict__ st)
{
    __shared__ int hist[256];
    __shared__ int off[256];
    int bh = blockIdx.x, tid = threadIdx.x;
    const int* bb = bkt + (size_t)bh * NHT;
    hist[tid] = 0;
    __syncthreads();
    for (int i = tid; i < NHT; i += 256) atomicAdd(&hist[bb[i]], 1);
    __syncthreads();
    if (tid == 0) {
        int s = 0;
        for (int i = 0; i < 256; i++) { off[i] = s; s += hist[i]; }
    }
    __syncthreads();
    // bucket beta lives entirely inside hash round h = beta/NB; tickers there
    // are in increasing pos order -> sequential scan is stable sort.
    int beta = tid, h = tid >> 5;
    int o = off[beta];
    int* out2 = st + (size_t)bh * NHT;
    int base = h * T_;
    for (int k = 0; k < T_; k++)
        if (bb[base + k] == beta) out2[o++] = base + k;
}

// ------------------------- chunked LSH attention ----------------------------
#define RS 68
#define DS 129
__global__ __launch_bounds__(128) void attn_kernel(
    const float* __restrict__ qk, const float* __restrict__ vg,
    const int* __restrict__ st, float* __restrict__ og, float* __restrict__ lgg)
{
    extern __shared__ float sm[];
    float* r     = sm;                  // 128 x RS   raw qk rows (q + keys)
    float* vv    = r + 128 * RS;        // 128 x 64   v rows
    float* dots  = vv + 128 * 64;       // 64 x DS
    float* inorm = dots + 64 * DS;      // 128
    float* logit = inorm + 128;         // 64
    int*   kpos  = (int*)(logit + 64);  // 128
    int*   qh    = kpos + 128;          // 64

    int tid = threadIdx.x;
    int bh = blockIdx.x >> 8, c = blockIdx.x & 255;
    int cp = (c + NCH - 1) & 255;

    {
        int lc = (tid < 64) ? c : cp;
        int tk = st[(size_t)bh * NHT + lc * 64 + (tid & 63)];
        kpos[tid] = tk & (T_ - 1);
        if (tid < 64) qh[tid] = tk >> 11;
    }
    __syncthreads();

    const float* qb = qk + ((size_t)bh << 17);
    const float* vb = vg + ((size_t)bh << 17);
    for (int it = 0; it < 64; it++) {
        int idx = it * 128 + tid;
        int jj = idx >> 6, d = idx & 63;
        int pos = kpos[jj];
        r[jj * RS + d]    = qb[(pos << 6) + d];
        vv[(jj << 6) + d] = vb[(pos << 6) + d];
    }
    __syncthreads();
    {
        float s = 0.f, cs = 0.f;
        #pragma unroll 8
        for (int d = 0; d < 64; d++) {
            float x = r[tid * RS + d];
            float p = x * x; KAHAN(s, cs, p);
        }
        inorm[tid] = 1.f / fmaxf(sqrtf(s + cs), 1e-12f);
    }
    __syncthreads();

    int tx = tid & 15, ty = tid >> 4;
    u64 acc[8][4], cmp[8][4];
    #pragma unroll
    for (int i = 0; i < 8; i++)
        #pragma unroll
        for (int m = 0; m < 4; m++) { acc[i][m] = 0ull; cmp[i][m] = 0ull; }

    for (int d = 0; d < 64; d++) {
        u64 kv2[4];
        #pragma unroll
        for (int m = 0; m < 4; m++)
            kv2[m] = pk2(r[(tx + 32 * m) * RS + d], r[(tx + 32 * m + 16) * RS + d]);
        #pragma unroll
        for (int i = 0; i < 8; i++) {
            float qs = r[(ty * 8 + i) * RS + d];
            u64 qv = pk2(qs, qs);
            #pragma unroll
            for (int m = 0; m < 4; m++) {
                u64 p = mul2(qv, kv2[m]);
                KAHAN2(acc[i][m], cmp[i][m], p);
            }
        }
    }
    #pragma unroll
    for (int i = 0; i < 8; i++) {
        int row = ty * 8 + i; int rp = kpos[row];
        #pragma unroll
        for (int mm = 0; mm < 4; mm++) {
            float2 s = upk2(acc[i][mm]);
            float2 cc = upk2(cmp[i][mm]);
            float dv2[2] = {s.x + cc.x, s.y + cc.y};
            #pragma unroll
            for (int q = 0; q < 2; q++) {
                int col = tx + 32 * mm + 16 * q;
                float dv = dv2[q] * inorm[col] * 0.125f;
                if (rp == kpos[col]) dv = -5e4f;
                dots[row * DS + col] = dv;
            }
        }
    }
    __syncthreads();

    if (tid < 64) {
        float mx = -1e30f;
        #pragma unroll 8
        for (int j2 = 0; j2 < 128; j2++) mx = fmaxf(mx, dots[tid * DS + j2]);
        float s = 0.f;
        #pragma unroll 8
        for (int j2 = 0; j2 < 128; j2++) s += expf(dots[tid * DS + j2] - mx);
        float lg = mx + logf(s);
        logit[tid] = lg;
        lgg[((size_t)bh * NH + qh[tid]) * T_ + kpos[tid]] = lg;
    }
    __syncthreads();
    for (int it = 0; it < 64; it++) {
        int idx = it * 128 + tid; int i = idx >> 7, j2 = idx & 127;
        dots[i * DS + j2] = expf(dots[i * DS + j2] - logit[i]);
    }
    __syncthreads();

    u64 a2[8][2], c2[8][2];
    #pragma unroll
    for (int i = 0; i < 8; i++)
        #pragma unroll
        for (int m = 0; m < 2; m++) { a2[i][m] = 0ull; c2[i][m] = 0ull; }
    for (int j2 = 0; j2 < 128; j2++) {
        u64 vw2[2];
        #pragma unroll
        for (int m = 0; m < 2; m++)
            vw2[m] = pk2(vv[(j2 << 6) + tx + 32 * m], vv[(j2 << 6) + tx + 32 * m + 16]);
        #pragma unroll
        for (int i = 0; i < 8; i++) {
            float ps = dots[(ty * 8 + i) * DS + j2];
            u64 pv = pk2(ps, ps);
            #pragma unroll
            for (int m = 0; m < 2; m++) {
                u64 p = mul2(pv, vw2[m]);
                KAHAN2(a2[i][m], c2[i][m], p);
            }
        }
    }
    #pragma unroll
    for (int i = 0; i < 8; i++) {
        int row = ty * 8 + i;
        size_t base = (((size_t)bh * NH + qh[row]) * T_ + kpos[row]) << 6;
        #pragma unroll
        for (int mm = 0; mm < 2; mm++) {
            float2 s = upk2(a2[i][mm]);
            float2 cc = upk2(c2[i][mm]);
            og[base + tx + 32 * mm]      = s.x + cc.x;
            og[base + tx + 32 * mm + 16] = s.y + cc.y;
        }
    }
}

// ------------------------- combine hash rounds ------------------------------
__global__ __launch_bounds__(64) void combine_kernel(
    const float* __restrict__ og, const float* __restrict__ lgg, float* __restrict__ at)
{
    __shared__ float w[8];
    int bh = blockIdx.x >> 11, pos = blockIdx.x & 2047;
    int tid = threadIdx.x;
    if (tid == 0) {
        float v[8]; float mx = -1e30f;
        #pragma unroll
        for (int h = 0; h < 8; h++) {
            v[h] = lgg[((size_t)bh * NH + h) * T_ + pos];
            mx = fmaxf(mx, v[h]);
        }
        float s = 0.f;
        #pragma unroll
        for (int h = 0; h < 8; h++) { v[h] = expf(v[h] - mx); s += v[h]; }
        float is = 1.f / s;
        #pragma unroll
        for (int h = 0; h < 8; h++) w[h] = v[h] * is;
    }
    __syncthreads();
    float acc = 0.f, cc = 0.f;
    #pragma unroll
    for (int h = 0; h < 8; h++) {
        float p = w[h] * og[(((size_t)bh * NH + h) * T_ + pos) * 64 + tid];
        KAHAN(acc, cc, p);
    }
    int b = bh >> 3, hd = bh & 7;
    at[((size_t)(b * T_ + pos)) * DIM + hd * 64 + tid] = acc + cc;
}

// ------------------------- frontend helpers ---------------------------------
__global__ void wt_kernel(const float* __restrict__ w, float* __restrict__ wT)
{
    int idx = blockIdx.x * 256 + threadIdx.x;     // KC*DIM
    int c = idx / DIM, o2 = idx - c * DIM;
    wT[idx] = (c < 687) ? w[(size_t)o2 * 687 + c] : 0.f;
}

__global__ void im2col_kernel(const float* __restrict__ spec, float* __restrict__ im)
{
    int idx = blockIdx.x * 256 + threadIdx.x;     // BT*KC
    int row = idx / KC, c = idx - row * KC;
    int b = row >> 11, t = row & 2047;
    float val = 0.f;
    if (c < 687) {
        int i = c / 3, k = c - i * 3;
        int tt = t + k - 1;
        if (tt >= 0 && tt < T_) val = spec[((size_t)b * T_ + tt) * 229 + i];
    }
    im[idx] = val;
}

__global__ void pe_kernel(float* __restrict__ x1, float* __restrict__ x2,
                          const float* __restrict__ per, const float* __restrict__ pec)
{
    int idx = blockIdx.x * 256 + threadIdx.x;     // BT*DIM
    int c = idx & 511;
    int t = (idx >> 9) & 2047;
    float p = (c < 256) ? per[(t >> 6) * 256 + c] : pec[(t & 63) * 256 + (c - 256)];
    float v = x1[idx] + p;
    x1[idx] = v; x2[idx] = v;
}

__global__ void avg_kernel(const float* __restrict__ a, const float* __restrict__ b,
                           float* __restrict__ y)
{
    int idx = blockIdx.x * 256 + threadIdx.x;
    y[idx] = 0.5f * (a[idx] + b[idx]);
}

// ------------------------- driver -------------------------------------------
extern "C" void kernel_launch(void* const* d_in, const int* in_sizes, int n_in,
                              void* d_out, int out_size)
{
    const float* spec   = (const float*)d_in[0];
    const float* conv_w = (const float*)d_in[1];
    const float* conv_b = (const float*)d_in[2];
    const float* pe_row = (const float*)d_in[3];
    const float* pe_col = (const float*)d_in[4];
    const float* lnA_g  = (const float*)d_in[5];
    const float* lnA_b  = (const float*)d_in[6];
    const float* wqk    = (const float*)d_in[7];
    const float* wv     = (const float*)d_in[8];
    const float* wo     = (const float*)d_in[9];
    const float* bo     = (const float*)d_in[10];
    const float* lnF_g  = (const float*)d_in[11];
    const float* lnF_b  = (const float*)d_in[12];
    const float* w1     = (const float*)d_in[13];
    const float* b1     = (const float*)d_in[14];
    const float* w2     = (const float*)d_in[15];
    const float* b2     = (const float*)d_in[16];
    const float* lin_w  = (const float*)d_in[17];
    const float* lin_b  = (const float*)d_in[18];
    const float* rot    = (const float*)d_in[19];
    float* out = (float*)d_out;

    float *x1, *x2, *tmp, *qk, *v, *at, *ff, *im, *wT, *o, *lg;
    int *bk, *st;
    cudaGetSymbolAddress((void**)&x1, g_x1);
    cudaGetSymbolAddress((void**)&x2, g_x2);
    cudaGetSymbolAddress((void**)&tmp, g_tmp);
    cudaGetSymbolAddress((void**)&qk, g_qk);
    cudaGetSymbolAddress((void**)&v,  g_v);
    cudaGetSymbolAddress((void**)&at, g_at);
    cudaGetSymbolAddress((void**)&ff, g_ffb);
    cudaGetSymbolAddress((void**)&im, g_im);
    cudaGetSymbolAddress((void**)&wT, g_wT);
    cudaGetSymbolAddress((void**)&o,  g_o);
    cudaGetSymbolAddress((void**)&lg, g_lg);
    cudaGetSymbolAddress((void**)&bk, g_bk);
    cudaGetSymbolAddress((void**)&st, g_st);

    size_t asmem = (size_t)(128 * RS + 128 * 64 + 64 * DS + 128 + 64 + 128 + 64) * 4;
    cudaFuncSetAttribute(attn_kernel, cudaFuncAttributeMaxDynamicSharedMemorySize, (int)asmem);

    // frontend: conv1d (im2col GEMM) + relu + axial positional embedding
    wt_kernel<<<(KC * DIM) / 256, 256>>>(conv_w, wT);
    im2col_kernel<<<(BT * KC) / 256, 256>>>(spec, im);
    sgemm<<<dim3(DIM / 64, BT / 128), 256>>>(im, wT, conv_b, nullptr, x1,
                                             BT, DIM, KC, 1, 0);
    pe_kernel<<<(BT * DIM) / 256, 256>>>(x1, x2, pe_row, pe_col);

    for (int i = 0; i < 8; i++) {
        ln_kernel<<<BT, 256>>>(x2, lnA_g + i * DIM, lnA_b + i * DIM, tmp);
        sgemm<<<dim3(8, 32), 256>>>(tmp, wqk + (size_t)i * DIM * DIM, nullptr, nullptr,
                                    qk, BT, DIM, DIM, 0, 1);
        sgemm<<<dim3(8, 32), 256>>>(tmp, wv + (size_t)i * DIM * DIM, nullptr, nullptr,
                                    v, BT, DIM, DIM, 0, 1);
        hash_kernel<<<BH * (T_ / TCH), 128>>>(qk, rot + (size_t)i * 64 * 128, bk);
        sort_kernel<<<BH, 256>>>(bk, st);
        attn_kernel<<<BH * NCH, 128, asmem>>>(qk, v, st, o, lg);
        combine_kernel<<<BH * T_, 64>>>(o, lg, at);
        sgemm<<<dim3(8, 32), 256>>>(at, wo + (size_t)i * DIM * DIM, bo + i * DIM,
                                    x1, x1, BT, DIM, DIM, 0, 0);
        ln_kernel<<<BT, 256>>>(x1, lnF_g + i * DIM, lnF_b + i * DIM, tmp);
        sgemm<<<dim3(FF / 64, 32), 256>>>(tmp, w1 + (size_t)i * DIM * FF, b1 + i * FF,
                                          nullptr, ff, BT, FF, DIM, 2, 0);
        sgemm<<<dim3(8, 32), 256>>>(ff, w2 + (size_t)i * DIM * FF, b2 + i * DIM,
                                    x2, x2, BT, DIM, FF, 0, 0);
    }

    avg_kernel<<<(BT * DIM) / 256, 256>>>(x1, x2, tmp);
    sgemm<<<dim3(2, 32), 256>>>(tmp, lin_w, lin_b, nullptr, out, BT, 88, DIM, 0, 0);
}

// round 4
// speedup vs baseline: 1.6488x; 1.6488x over previous
#include <cuda_runtime.h>
#include <math.h>

#define B_   2
#define T_   2048
#define BT   4096
#define DIM  512
#define H_   8
#define DH   64
#define NH   8
#define NB   32
#define NCH  256      // NH*NB chunks per bh
#define BH   16
#define NHT  16384    // NH*T
#define KC   704      // padded conv K (229*3=687 -> 704)
#define FF   2048

// scalar Kahan merge: sum s, compensation c, incoming value p
#define KAHAN(s, c, p) { float y_ = (p) - (c); float t_ = (s) + y_; (c) = (t_ - (s)) - y_; (s) = t_; }

// ------------------------- scratch (static device) -------------------------
__device__ float g_x1[BT*DIM];
__device__ float g_x2[BT*DIM];
__device__ float g_tmp[BT*DIM];
__device__ float g_qk[BT*DIM];
__device__ float g_v [BT*DIM];
__device__ float g_at[BT*DIM];
__device__ float g_ffb[BT*FF];
__device__ float g_im[BT*KC];
__device__ float g_wT[KC*DIM];
__device__ int   g_bk[BH*NHT];
__device__ int   g_st[BH*NHT];
__device__ float g_o [BH*NHT*DH];
__device__ float g_lg[BH*NHT];

// ------------------------- SGEMM: C = act(A@B + bias) + resid --------------
// Block-4 compensated accumulation: 4 plain FMAs into a block partial, then
// Kahan-merge the partial. A: MxK row-major, B: KxN row-major.
// BM=128, BN=64, BK=16, 256 threads. act: 0 none, 1 relu, 2 gelu(exact).
__global__ __launch_bounds__(256) void sgemm(
    const float* __restrict__ A, const float* __restrict__ Bm,
    const float* __restrict__ bias, const float* __restrict__ resid,
    float* __restrict__ C, int M, int N, int K, int act, int heads)
{
    __shared__ float As[16][132];
    __shared__ float Bs[16][64];
    const int tid = threadIdx.x;
    const int tx = tid & 15, ty = tid >> 4;
    const int m0 = blockIdx.y * 128, n0 = blockIdx.x * 64;

    float acc[8][4], cmp[8][4];
    #pragma unroll
    for (int i = 0; i < 8; i++)
        #pragma unroll
        for (int j = 0; j < 4; j++) { acc[i][j] = 0.f; cmp[i][j] = 0.f; }

    const int arow0 = tid >> 2, ac4 = (tid & 3) * 4;
    const int brow = tid >> 4, bc4 = (tid & 15) * 4;
    const int bcol = n0 + bc4;

    for (int k0 = 0; k0 < K; k0 += 16) {
        #pragma unroll
        for (int s = 0; s < 2; s++) {
            int row = arow0 + s * 64;
            float4 a = *(const float4*)(A + (size_t)(m0 + row) * K + k0 + ac4);
            As[ac4 + 0][row] = a.x; As[ac4 + 1][row] = a.y;
            As[ac4 + 2][row] = a.z; As[ac4 + 3][row] = a.w;
        }
        float4 bv;
        if (bcol < N) bv = *(const float4*)(Bm + (size_t)(k0 + brow) * N + bcol);
        else          bv = make_float4(0.f, 0.f, 0.f, 0.f);
        *(float4*)(&Bs[brow][bc4]) = bv;
        __syncthreads();
        #pragma unroll
        for (int kb = 0; kb < 4; kb++) {
            float pb[8][4];
            #pragma unroll
            for (int kk = 0; kk < 4; kk++) {
                int k = kb * 4 + kk;
                float4 a0 = *(const float4*)(&As[k][ty * 8]);
                float4 a1 = *(const float4*)(&As[k][ty * 8 + 4]);
                float4 bb = *(const float4*)(&Bs[k][tx * 4]);
                float av[8] = {a0.x, a0.y, a0.z, a0.w, a1.x, a1.y, a1.z, a1.w};
                float bw[4] = {bb.x, bb.y, bb.z, bb.w};
                if (kk == 0) {
                    #pragma unroll
                    for (int i = 0; i < 8; i++)
                        #pragma unroll
                        for (int j = 0; j < 4; j++) pb[i][j] = av[i] * bw[j];
                } else {
                    #pragma unroll
                    for (int i = 0; i < 8; i++)
                        #pragma unroll
                        for (int j = 0; j < 4; j++) pb[i][j] = fmaf(av[i], bw[j], pb[i][j]);
                }
            }
            #pragma unroll
            for (int i = 0; i < 8; i++)
                #pragma unroll
                for (int j = 0; j < 4; j++) KAHAN(acc[i][j], cmp[i][j], pb[i][j]);
        }
        __syncthreads();
    }

    #pragma unroll
    for (int i = 0; i < 8; i++) {
        int row = m0 + ty * 8 + i;
        #pragma unroll
        for (int j = 0; j < 4; j++) {
            int col = n0 + tx * 4 + j;
            if (col >= N) continue;
            float v = acc[i][j] + cmp[i][j];
            if (bias) v += bias[col];
            if (act == 1) v = fmaxf(v, 0.f);
            else if (act == 2) v = 0.5f * v * (1.f + erff(v * 0.70710678118654752f));
            if (resid) v += resid[(size_t)row * N + col];
            if (heads) {
                int b = row >> 11, t = row & 2047;
                int h = col >> 6, d = col & 63;
                C[((((size_t)b * H_ + h) * T_ + t) << 6) + d] = v;
            } else {
                C[(size_t)row * N + col] = v;
            }
        }
    }
}

// ------------------------- LayerNorm (row of 512) ---------------------------
__global__ __launch_bounds__(256) void ln_kernel(
    const float* __restrict__ x, const float* __restrict__ g,
    const float* __restrict__ bb, float* __restrict__ y)
{
    __shared__ float sh[8];
    int row = blockIdx.x, tid = threadIdx.x;
    const float* xr = x + (size_t)row * DIM;
    float v0 = xr[tid], v1 = xr[tid + 256];
    float s = v0 + v1;
    #pragma unroll
    for (int o = 16; o; o >>= 1) s += __shfl_down_sync(0xffffffffu, s, o);
    if ((tid & 31) == 0) sh[tid >> 5] = s;
    __syncthreads();
    if (tid < 32) {
        float t = (tid < 8) ? sh[tid] : 0.f;
        #pragma unroll
        for (int o = 4; o; o >>= 1) t += __shfl_down_sync(0xffffffffu, t, o);
        if (tid == 0) sh[0] = t;
    }
    __syncthreads();
    float mean = sh[0] * (1.f / DIM);
    __syncthreads();
    float d0 = v0 - mean, d1 = v1 - mean;
    float s2 = d0 * d0 + d1 * d1;
    #pragma unroll
    for (int o = 16; o; o >>= 1) s2 += __shfl_down_sync(0xffffffffu, s2, o);
    if ((tid & 31) == 0) sh[tid >> 5] = s2;
    __syncthreads();
    if (tid < 32) {
        float t = (tid < 8) ? sh[tid] : 0.f;
        #pragma unroll
        for (int o = 4; o; o >>= 1) t += __shfl_down_sync(0xffffffffu, t, o);
        if (tid == 0) sh[0] = t;
    }
    __syncthreads();
    float inv = 1.f / sqrtf(sh[0] * (1.f / DIM) + 1e-5f);
    float* yr = y + (size_t)row * DIM;
    yr[tid]       = d0 * inv * g[tid]       + bb[tid];
    yr[tid + 256] = d1 * inv * g[tid + 256] + bb[tid + 256];
}

// ------------------------- LSH hashing (full Kahan: decides argmax) ---------
#define TCH 16
__global__ __launch_bounds__(128) void hash_kernel(
    const float* __restrict__ qk, const float* __restrict__ rot, int* __restrict__ bkt)
{
    __shared__ float q[4][DH];
    int blk = blockIdx.x;
    int bh = blk / (T_ / TCH);
    int t0 = (blk % (T_ / TCH)) * TCH;
    int tid = threadIdx.x;
    int h = tid >> 4, j = tid & 15;
    float rv[64];
    #pragma unroll
    for (int f = 0; f < 64; f++) rv[f] = rot[f * 128 + h * 16 + j];

    for (int tg = 0; tg < TCH; tg += 4) {
        __syncthreads();
        for (int idx = tid; idx < 4 * DH; idx += 128) {
            int r = idx >> 6, d = idx & 63;
            q[r][d] = qk[((size_t)bh * T_ + t0 + tg + r) * DH + d];
        }
        __syncthreads();
        float a0 = 0.f, a1 = 0.f, a2 = 0.f, a3 = 0.f;
        float c0 = 0.f, c1 = 0.f, c2 = 0.f, c3 = 0.f;
        #pragma unroll
        for (int f = 0; f < 64; f++) {
            float r = rv[f];
            float p0 = q[0][f] * r; KAHAN(a0, c0, p0);
            float p1 = q[1][f] * r; KAHAN(a1, c1, p1);
            float p2 = q[2][f] * r; KAHAN(a2, c2, p2);
            float p3 = q[3][f] * r; KAHAN(a3, c3, p3);
        }
        float vals[4] = {a0 + c0, a1 + c1, a2 + c2, a3 + c3};
        #pragma unroll
        for (int r = 0; r < 4; r++) {
            float v = vals[r]; int idx = j;
            float nv = -v;
            if (nv > v) { v = nv; idx = j + 16; }   // ties keep +r (smaller index)
            #pragma unroll
            for (int o = 8; o; o >>= 1) {
                float ov = __shfl_down_sync(0xffffffffu, v, o, 16);
                int   oi = __shfl_down_sync(0xffffffffu, idx, o, 16);
                if (ov > v || (ov == v && oi < idx)) { v = ov; idx = oi; }
            }
            if (j == 0) bkt[(size_t)bh * NHT + h * T_ + t0 + tg + r] = idx + h * NB;
        }
    }
}

// ------------------------- stable counting sort by (bucket, pos) ------------
__global__ __launch_bounds__(256) void sort_kernel(
    const int* __restrict__ bkt, int* __restrict__ st)
{
    __shared__ int hist[256];
    __shared__ int off[256];
    int bh = blockIdx.x, tid = threadIdx.x;
    const int* bb = bkt + (size_t)bh * NHT;
    hist[tid] = 0;
    __syncthreads();
    for (int i = tid; i < NHT; i += 256) atomicAdd(&hist[bb[i]], 1);
    __syncthreads();
    if (tid == 0) {
        int s = 0;
        for (int i = 0; i < 256; i++) { off[i] = s; s += hist[i]; }
    }
    __syncthreads();
    // bucket beta lives entirely inside hash round h = beta/NB; tickers there
    // are in increasing pos order -> sequential scan is stable sort.
    int beta = tid, h = tid >> 5;
    int o = off[beta];
    int* out2 = st + (size_t)bh * NHT;
    int base = h * T_;
    for (int k = 0; k < T_; k++)
        if (bb[base + k] == beta) out2[o++] = base + k;
}

// ------------------------- chunked LSH attention ----------------------------
#define RS 68
#define DS 129
__global__ __launch_bounds__(128) void attn_kernel(
    const float* __restrict__ qk, const float* __restrict__ vg,
    const int* __restrict__ st, float* __restrict__ og, float* __restrict__ lgg)
{
    extern __shared__ float sm[];
    float* r     = sm;                  // 128 x RS   raw qk rows (q + keys)
    float* vv    = r + 128 * RS;        // 128 x 64   v rows
    float* dots  = vv + 128 * 64;       // 64 x DS
    float* inorm = dots + 64 * DS;      // 128
    float* logit = inorm + 128;         // 64
    int*   kpos  = (int*)(logit + 64);  // 128
    int*   qh    = kpos + 128;          // 64

    int tid = threadIdx.x;
    int bh = blockIdx.x >> 8, c = blockIdx.x & 255;
    int cp = (c + NCH - 1) & 255;

    {
        int lc = (tid < 64) ? c : cp;
        int tk = st[(size_t)bh * NHT + lc * 64 + (tid & 63)];
        kpos[tid] = tk & (T_ - 1);
        if (tid < 64) qh[tid] = tk >> 11;
    }
    __syncthreads();

    const float* qb = qk + ((size_t)bh << 17);
    const float* vb = vg + ((size_t)bh << 17);
    for (int it = 0; it < 64; it++) {
        int idx = it * 128 + tid;
        int jj = idx >> 6, d = idx & 63;
        int pos = kpos[jj];
        r[jj * RS + d]    = qb[(pos << 6) + d];
        vv[(jj << 6) + d] = vb[(pos << 6) + d];
    }
    __syncthreads();
    {
        float s = 0.f, cs = 0.f;
        #pragma unroll 8
        for (int d = 0; d < 64; d++) {
            float x = r[tid * RS + d];
            float p = x * x; KAHAN(s, cs, p);
        }
        inorm[tid] = 1.f / fmaxf(sqrtf(s + cs), 1e-12f);
    }
    __syncthreads();

    int tx = tid & 15, ty = tid >> 4;
    float acc[8][8], cmp[8][8];
    #pragma unroll
    for (int i = 0; i < 8; i++)
        #pragma unroll
        for (int m = 0; m < 8; m++) { acc[i][m] = 0.f; cmp[i][m] = 0.f; }

    for (int db = 0; db < 16; db++) {
        float kvb[4][8];
        #pragma unroll
        for (int dd = 0; dd < 4; dd++)
            #pragma unroll
            for (int m = 0; m < 8; m++)
                kvb[dd][m] = r[(tx + 16 * m) * RS + db * 4 + dd];
        #pragma unroll
        for (int i = 0; i < 8; i++) {
            float qv[4];
            #pragma unroll
            for (int dd = 0; dd < 4; dd++) qv[dd] = r[(ty * 8 + i) * RS + db * 4 + dd];
            float pb[8];
            #pragma unroll
            for (int m = 0; m < 8; m++) {
                float p = qv[0] * kvb[0][m];
                p = fmaf(qv[1], kvb[1][m], p);
                p = fmaf(qv[2], kvb[2][m], p);
                p = fmaf(qv[3], kvb[3][m], p);
                pb[m] = p;
            }
            #pragma unroll
            for (int m = 0; m < 8; m++) KAHAN(acc[i][m], cmp[i][m], pb[m]);
        }
    }
    #pragma unroll
    for (int i = 0; i < 8; i++) {
        int row = ty * 8 + i; int rp = kpos[row];
        #pragma unroll
        for (int m = 0; m < 8; m++) {
            int col = tx + 16 * m;
            float dv = (acc[i][m] + cmp[i][m]) * inorm[col] * 0.125f;
            if (rp == kpos[col]) dv = -5e4f;
            dots[row * DS + col] = dv;
        }
    }
    __syncthreads();

    if (tid < 64) {
        float mx = -1e30f;
        #pragma unroll 8
        for (int j2 = 0; j2 < 128; j2++) mx = fmaxf(mx, dots[tid * DS + j2]);
        float s = 0.f;
        #pragma unroll 8
        for (int j2 = 0; j2 < 128; j2++) s += expf(dots[tid * DS + j2] - mx);
        float lg = mx + logf(s);
        logit[tid] = lg;
        lgg[((size_t)bh * NH + qh[tid]) * T_ + kpos[tid]] = lg;
    }
    __syncthreads();
    for (int it = 0; it < 64; it++) {
        int idx = it * 128 + tid; int i = idx >> 7, j2 = idx & 127;
        dots[i * DS + j2] = expf(dots[i * DS + j2] - logit[i]);
    }
    __syncthreads();

    float a2[8][4], c2[8][4];
    #pragma unroll
    for (int i = 0; i < 8; i++)
        #pragma unroll
        for (int m = 0; m < 4; m++) { a2[i][m] = 0.f; c2[i][m] = 0.f; }
    for (int jb = 0; jb < 32; jb++) {
        float vwb[4][4];
        #pragma unroll
        for (int dd = 0; dd < 4; dd++)
            #pragma unroll
            for (int m = 0; m < 4; m++)
                vwb[dd][m] = vv[(((jb * 4 + dd)) << 6) + tx + 16 * m];
        #pragma unroll
        for (int i = 0; i < 8; i++) {
            float pv[4];
            #pragma unroll
            for (int dd = 0; dd < 4; dd++) pv[dd] = dots[(ty * 8 + i) * DS + jb * 4 + dd];
            float pb[4];
            #pragma unroll
            for (int m = 0; m < 4; m++) {
                float p = pv[0] * vwb[0][m];
                p = fmaf(pv[1], vwb[1][m], p);
                p = fmaf(pv[2], vwb[2][m], p);
                p = fmaf(pv[3], vwb[3][m], p);
                pb[m] = p;
            }
            #pragma unroll
            for (int m = 0; m < 4; m++) KAHAN(a2[i][m], c2[i][m], pb[m]);
        }
    }
    #pragma unroll
    for (int i = 0; i < 8; i++) {
        int row = ty * 8 + i;
        size_t base = (((size_t)bh * NH + qh[row]) * T_ + kpos[row]) << 6;
        #pragma unroll
        for (int m = 0; m < 4; m++) og[base + tx + 16 * m] = a2[i][m] + c2[i][m];
    }
}

// ------------------------- combine hash rounds ------------------------------
__global__ __launch_bounds__(64) void combine_kernel(
    const float* __restrict__ og, const float* __restrict__ lgg, float* __restrict__ at)
{
    __shared__ float w[8];
    int bh = blockIdx.x >> 11, pos = blockIdx.x & 2047;
    int tid = threadIdx.x;
    if (tid == 0) {
        float v[8]; float mx = -1e30f;
        #pragma unroll
        for (int h = 0; h < 8; h++) {
            v[h] = lgg[((size_t)bh * NH + h) * T_ + pos];
            mx = fmaxf(mx, v[h]);
        }
        float s = 0.f;
        #pragma unroll
        for (int h = 0; h < 8; h++) { v[h] = expf(v[h] - mx); s += v[h]; }
        float is = 1.f / s;
        #pragma unroll
        for (int h = 0; h < 8; h++) w[h] = v[h] * is;
    }
    __syncthreads();
    float acc = 0.f, cc = 0.f;
    #pragma unroll
    for (int h = 0; h < 8; h++) {
        float p = w[h] * og[(((size_t)bh * NH + h) * T_ + pos) * 64 + tid];
        KAHAN(acc, cc, p);
    }
    int b = bh >> 3, hd = bh & 7;
    at[((size_t)(b * T_ + pos)) * DIM + hd * 64 + tid] = acc + cc;
}

// ------------------------- frontend helpers ---------------------------------
__global__ void wt_kernel(const float* __restrict__ w, float* __restrict__ wT)
{
    int idx = blockIdx.x * 256 + threadIdx.x;     // KC*DIM
    int c = idx / DIM, o2 = idx - c * DIM;
    wT[idx] = (c < 687) ? w[(size_t)o2 * 687 + c] : 0.f;
}

__global__ void im2col_kernel(const float* __restrict__ spec, float* __restrict__ im)
{
    int idx = blockIdx.x * 256 + threadIdx.x;     // BT*KC
    int row = idx / KC, c = idx - row * KC;
    int b = row >> 11, t = row & 2047;
    float val = 0.f;
    if (c < 687) {
        int i = c / 3, k = c - i * 3;
        int tt = t + k - 1;
        if (tt >= 0 && tt < T_) val = spec[((size_t)b * T_ + tt) * 229 + i];
    }
    im[idx] = val;
}

__global__ void pe_kernel(float* __restrict__ x1, float* __restrict__ x2,
                          const float* __restrict__ per, const float* __restrict__ pec)
{
    int idx = blockIdx.x * 256 + threadIdx.x;     // BT*DIM
    int c = idx & 511;
    int t = (idx >> 9) & 2047;
    float p = (c < 256) ? per[(t >> 6) * 256 + c] : pec[(t & 63) * 256 + (c - 256)];
    float v = x1[idx] + p;
    x1[idx] = v; x2[idx] = v;
}

__global__ void avg_kernel(const float* __restrict__ a, const float* __restrict__ b,
                           float* __restrict__ y)
{
    int idx = blockIdx.x * 256 + threadIdx.x;
    y[idx] = 0.5f * (a[idx] + b[idx]);
}

// ------------------------- driver -------------------------------------------
extern "C" void kernel_launch(void* const* d_in, const int* in_sizes, int n_in,
                              void* d_out, int out_size)
{
    const float* spec   = (const float*)d_in[0];
    const float* conv_w = (const float*)d_in[1];
    const float* conv_b = (const float*)d_in[2];
    const float* pe_row = (const float*)d_in[3];
    const float* pe_col = (const float*)d_in[4];
    const float* lnA_g  = (const float*)d_in[5];
    const float* lnA_b  = (const float*)d_in[6];
    const float* wqk    = (const float*)d_in[7];
    const float* wv     = (const float*)d_in[8];
    const float* wo     = (const float*)d_in[9];
    const float* bo     = (const float*)d_in[10];
    const float* lnF_g  = (const float*)d_in[11];
    const float* lnF_b  = (const float*)d_in[12];
    const float* w1     = (const float*)d_in[13];
    const float* b1     = (const float*)d_in[14];
    const float* w2     = (const float*)d_in[15];
    const float* b2     = (const float*)d_in[16];
    const float* lin_w  = (const float*)d_in[17];
    const float* lin_b  = (const float*)d_in[18];
    const float* rot    = (const float*)d_in[19];
    float* out = (float*)d_out;

    float *x1, *x2, *tmp, *qk, *v, *at, *ff, *im, *wT, *o, *lg;
    int *bk, *st;
    cudaGetSymbolAddress((void**)&x1, g_x1);
    cudaGetSymbolAddress((void**)&x2, g_x2);
    cudaGetSymbolAddress((void**)&tmp, g_tmp);
    cudaGetSymbolAddress((void**)&qk, g_qk);
    cudaGetSymbolAddress((void**)&v,  g_v);
    cudaGetSymbolAddress((void**)&at, g_at);
    cudaGetSymbolAddress((void**)&ff, g_ffb);
    cudaGetSymbolAddress((void**)&im, g_im);
    cudaGetSymbolAddress((void**)&wT, g_wT);
    cudaGetSymbolAddress((void**)&o,  g_o);
    cudaGetSymbolAddress((void**)&lg, g_lg);
    cudaGetSymbolAddress((void**)&bk, g_bk);
    cudaGetSymbolAddress((void**)&st, g_st);

    size_t asmem = (size_t)(128 * RS + 128 * 64 + 64 * DS + 128 + 64 + 128 + 64) * 4;
    cudaFuncSetAttribute(attn_kernel, cudaFuncAttributeMaxDynamicSharedMemorySize, (int)asmem);

    // frontend: conv1d (im2col GEMM) + relu + axial positional embedding
    wt_kernel<<<(KC * DIM) / 256, 256>>>(conv_w, wT);
    im2col_kernel<<<(BT * KC) / 256, 256>>>(spec, im);
    sgemm<<<dim3(DIM / 64, BT / 128), 256>>>(im, wT, conv_b, nullptr, x1,
                                             BT, DIM, KC, 1, 0);
    pe_kernel<<<(BT * DIM) / 256, 256>>>(x1, x2, pe_row, pe_col);

    for (int i = 0; i < 8; i++) {
        ln_kernel<<<BT, 256>>>(x2, lnA_g + i * DIM, lnA_b + i * DIM, tmp);
        sgemm<<<dim3(8, 32), 256>>>(tmp, wqk + (size_t)i * DIM * DIM, nullptr, nullptr,
                                    qk, BT, DIM, DIM, 0, 1);
        sgemm<<<dim3(8, 32), 256>>>(tmp, wv + (size_t)i * DIM * DIM, nullptr, nullptr,
                                    v, BT, DIM, DIM, 0, 1);
        hash_kernel<<<BH * (T_ / TCH), 128>>>(qk, rot + (size_t)i * 64 * 128, bk);
        sort_kernel<<<BH, 256>>>(bk, st);
        attn_kernel<<<BH * NCH, 128, asmem>>>(qk, v, st, o, lg);
        combine_kernel<<<BH * T_, 64>>>(o, lg, at);
        sgemm<<<dim3(8, 32), 256>>>(at, wo + (size_t)i * DIM * DIM, bo + i * DIM,
                                    x1, x1, BT, DIM, DIM, 0, 0);
        ln_kernel<<<BT, 256>>>(x1, lnF_g + i * DIM, lnF_b + i * DIM, tmp);
        sgemm<<<dim3(FF / 64, 32), 256>>>(tmp, w1 + (size_t)i * DIM * FF, b1 + i * FF,
                                          nullptr, ff, BT, FF, DIM, 2, 0);
        sgemm<<<dim3(8, 32), 256>>>(ff, w2 + (size_t)i * DIM * FF, b2 + i * DIM,
                                    x2, x2, BT, DIM, FF, 0, 0);
    }

    avg_kernel<<<(BT * DIM) / 256, 256>>>(x1, x2, tmp);
    sgemm<<<dim3(2, 32), 256>>>(tmp, lin_w, lin_b, nullptr, out, BT, 88, DIM, 0, 0);
}

// round 5
// speedup vs baseline: 1.7324x; 1.0507x over previous
#include <cuda_runtime.h>
#include <math.h>

#define B_   2
#define T_   2048
#define BT   4096
#define DIM  512
#define H_   8
#define DH   64
#define NH   8
#define NB   32
#define NCH  256      // NH*NB chunks per bh
#define BH   16
#define NHT  16384    // NH*T
#define KC   704      // padded conv K (229*3=687 -> 704)
#define FF   2048

// scalar Kahan merge: sum s, compensation c, incoming value p
#define KAHAN(s, c, p) { float y_ = (p) - (c); float t_ = (s) + y_; (c) = (t_ - (s)) - y_; (s) = t_; }

// ------------------------- scratch (static device) -------------------------
__device__ float g_x1[BT*DIM];
__device__ float g_x2[BT*DIM];
__device__ float g_tmp[BT*DIM];
__device__ float g_qk[BT*DIM];
__device__ float g_v [BT*DIM];
__device__ float g_at[BT*DIM];
__device__ float g_ffb[BT*FF];
__device__ float g_im[BT*KC];
__device__ float g_wT[KC*DIM];
__device__ int   g_bk[BH*NHT];
__device__ int   g_st[BH*NHT];
__device__ float g_o [BH*NHT*DH];
__device__ float g_lg[BH*NHT];

// ------------------------- SGEMM: C = act(A@B + bias) + resid --------------
// Block-8 compensated accumulation: 8 plain FMAs into a block partial, then
// one Kahan merge. BM=64, BN=64, BK=16, 256 threads, 4x4 microtile.
// act: 0 none, 1 relu, 2 gelu(exact). heads: output permuted to (b,H,t,DH).
// Nsplit>0: blocks with n0>=Nsplit use Bm2/C2 (fused dual-weight GEMM).
__global__ __launch_bounds__(256) void sgemm(
    const float* __restrict__ A, const float* __restrict__ Bm,
    const float* __restrict__ bias, const float* __restrict__ resid,
    float* __restrict__ C, int M, int N, int K, int act, int heads,
    const float* __restrict__ Bm2, float* __restrict__ C2, int Nsplit)
{
    __shared__ float As[16][68];
    __shared__ float Bs[16][64];
    const int tid = threadIdx.x;
    const int tx = tid & 15, ty = tid >> 4;
    const int m0 = blockIdx.y * 64;
    int n0 = blockIdx.x * 64;
    if (Nsplit && n0 >= Nsplit) { Bm = Bm2; C = C2; n0 -= Nsplit; }

    float acc[4][4], cmp[4][4];
    #pragma unroll
    for (int i = 0; i < 4; i++)
        #pragma unroll
        for (int j = 0; j < 4; j++) { acc[i][j] = 0.f; cmp[i][j] = 0.f; }

    const int arow = tid >> 2, ac4 = (tid & 3) * 4;
    const int brow = tid >> 4, bc4 = (tid & 15) * 4;
    const int bcol = n0 + bc4;

    for (int k0 = 0; k0 < K; k0 += 16) {
        {
            float4 a = *(const float4*)(A + (size_t)(m0 + arow) * K + k0 + ac4);
            As[ac4 + 0][arow] = a.x; As[ac4 + 1][arow] = a.y;
            As[ac4 + 2][arow] = a.z; As[ac4 + 3][arow] = a.w;
        }
        float4 bv;
        if (bcol < N) bv = *(const float4*)(Bm + (size_t)(k0 + brow) * N + bcol);
        else          bv = make_float4(0.f, 0.f, 0.f, 0.f);
        *(float4*)(&Bs[brow][bc4]) = bv;
        __syncthreads();
        #pragma unroll
        for (int kb = 0; kb < 2; kb++) {
            float pb[4][4];
            #pragma unroll
            for (int kk = 0; kk < 8; kk++) {
                int k = kb * 8 + kk;
                float4 a4 = *(const float4*)(&As[k][ty * 4]);
                float4 b4 = *(const float4*)(&Bs[k][tx * 4]);
                float av[4] = {a4.x, a4.y, a4.z, a4.w};
                float bw[4] = {b4.x, b4.y, b4.z, b4.w};
                if (kk == 0) {
                    #pragma unroll
                    for (int i = 0; i < 4; i++)
                        #pragma unroll
                        for (int j = 0; j < 4; j++) pb[i][j] = av[i] * bw[j];
                } else {
                    #pragma unroll
                    for (int i = 0; i < 4; i++)
                        #pragma unroll
                        for (int j = 0; j < 4; j++) pb[i][j] = fmaf(av[i], bw[j], pb[i][j]);
                }
            }
            #pragma unroll
            for (int i = 0; i < 4; i++)
                #pragma unroll
                for (int j = 0; j < 4; j++) KAHAN(acc[i][j], cmp[i][j], pb[i][j]);
        }
        __syncthreads();
    }

    #pragma unroll
    for (int i = 0; i < 4; i++) {
        int row = m0 + ty * 4 + i;
        #pragma unroll
        for (int j = 0; j < 4; j++) {
            int col = n0 + tx * 4 + j;
            if (col >= N) continue;
            float v = acc[i][j] + cmp[i][j];
            if (bias) v += bias[col];
            if (act == 1) v = fmaxf(v, 0.f);
            else if (act == 2) v = 0.5f * v * (1.f + erff(v * 0.70710678118654752f));
            if (resid) v += resid[(size_t)row * N + col];
            if (heads) {
                int b = row >> 11, t = row & 2047;
                int h = col >> 6, d = col & 63;
                C[((((size_t)b * H_ + h) * T_ + t) << 6) + d] = v;
            } else {
                C[(size_t)row * N + col] = v;
            }
        }
    }
}

// ------------------------- LayerNorm (row of 512) ---------------------------
__global__ __launch_bounds__(256) void ln_kernel(
    const float* __restrict__ x, const float* __restrict__ g,
    const float* __restrict__ bb, float* __restrict__ y)
{
    __shared__ float sh[8];
    int row = blockIdx.x, tid = threadIdx.x;
    const float* xr = x + (size_t)row * DIM;
    float v0 = xr[tid], v1 = xr[tid + 256];
    float s = v0 + v1;
    #pragma unroll
    for (int o = 16; o; o >>= 1) s += __shfl_down_sync(0xffffffffu, s, o);
    if ((tid & 31) == 0) sh[tid >> 5] = s;
    __syncthreads();
    if (tid < 32) {
        float t = (tid < 8) ? sh[tid] : 0.f;
        #pragma unroll
        for (int o = 4; o; o >>= 1) t += __shfl_down_sync(0xffffffffu, t, o);
        if (tid == 0) sh[0] = t;
    }
    __syncthreads();
    float mean = sh[0] * (1.f / DIM);
    __syncthreads();
    float d0 = v0 - mean, d1 = v1 - mean;
    float s2 = d0 * d0 + d1 * d1;
    #pragma unroll
    for (int o = 16; o; o >>= 1) s2 += __shfl_down_sync(0xffffffffu, s2, o);
    if ((tid & 31) == 0) sh[tid >> 5] = s2;
    __syncthreads();
    if (tid < 32) {
        float t = (tid < 8) ? sh[tid] : 0.f;
        #pragma unroll
        for (int o = 4; o; o >>= 1) t += __shfl_down_sync(0xffffffffu, t, o);
        if (tid == 0) sh[0] = t;
    }
    __syncthreads();
    float inv = 1.f / sqrtf(sh[0] * (1.f / DIM) + 1e-5f);
    float* yr = y + (size_t)row * DIM;
    yr[tid]       = d0 * inv * g[tid]       + bb[tid];
    yr[tid + 256] = d1 * inv * g[tid + 256] + bb[tid + 256];
}

// ------------------------- LSH hashing (full Kahan: decides argmax) ---------
#define TCH 16
__global__ __launch_bounds__(128) void hash_kernel(
    const float* __restrict__ qk, const float* __restrict__ rot, int* __restrict__ bkt)
{
    __shared__ float q[4][DH];
    int blk = blockIdx.x;
    int bh = blk / (T_ / TCH);
    int t0 = (blk % (T_ / TCH)) * TCH;
    int tid = threadIdx.x;
    int h = tid >> 4, j = tid & 15;
    float rv[64];
    #pragma unroll
    for (int f = 0; f < 64; f++) rv[f] = rot[f * 128 + h * 16 + j];

    for (int tg = 0; tg < TCH; tg += 4) {
        __syncthreads();
        for (int idx = tid; idx < 4 * DH; idx += 128) {
            int r = idx >> 6, d = idx & 63;
            q[r][d] = qk[((size_t)bh * T_ + t0 + tg + r) * DH + d];
        }
        __syncthreads();
        float a0 = 0.f, a1 = 0.f, a2 = 0.f, a3 = 0.f;
        float c0 = 0.f, c1 = 0.f, c2 = 0.f, c3 = 0.f;
        #pragma unroll
        for (int f = 0; f < 64; f++) {
            float r = rv[f];
            float p0 = q[0][f] * r; KAHAN(a0, c0, p0);
            float p1 = q[1][f] * r; KAHAN(a1, c1, p1);
            float p2 = q[2][f] * r; KAHAN(a2, c2, p2);
            float p3 = q[3][f] * r; KAHAN(a3, c3, p3);
        }
        float vals[4] = {a0 + c0, a1 + c1, a2 + c2, a3 + c3};
        #pragma unroll
        for (int r = 0; r < 4; r++) {
            float v = vals[r]; int idx = j;
            float nv = -v;
            if (nv > v) { v = nv; idx = j + 16; }   // ties keep +r (smaller index)
            #pragma unroll
            for (int o = 8; o; o >>= 1) {
                float ov = __shfl_down_sync(0xffffffffu, v, o, 16);
                int   oi = __shfl_down_sync(0xffffffffu, idx, o, 16);
                if (ov > v || (ov == v && oi < idx)) { v = ov; idx = oi; }
            }
            if (j == 0) bkt[(size_t)bh * NHT + h * T_ + t0 + tg + r] = idx + h * NB;
        }
    }
}

// ------------------------- stable counting sort by (bucket, pos) ------------
__global__ __launch_bounds__(256) void sort_kernel(
    const int* __restrict__ bkt, int* __restrict__ st)
{
    __shared__ int hist[256];
    __shared__ int off[256];
    int bh = blockIdx.x, tid = threadIdx.x;
    const int* bb = bkt + (size_t)bh * NHT;
    hist[tid] = 0;
    __syncthreads();
    for (int i = tid; i < NHT; i += 256) atomicAdd(&hist[bb[i]], 1);
    __syncthreads();
    if (tid == 0) {
        int s = 0;
        for (int i = 0; i < 256; i++) { off[i] = s; s += hist[i]; }
    }
    __syncthreads();
    // bucket beta lives entirely inside hash round h = beta/NB; tickers there
    // are in increasing pos order -> sequential scan is stable sort.
    int beta = tid, h = tid >> 5;
    int o = off[beta];
    int* out2 = st + (size_t)bh * NHT;
    int base = h * T_;
    for (int k = 0; k < T_; k++)
        if (bb[base + k] == beta) out2[o++] = base + k;
}

// ------------------------- chunked LSH attention ----------------------------
#define RS 68
#define DS 129
__global__ __launch_bounds__(128) void attn_kernel(
    const float* __restrict__ qk, const float* __restrict__ vg,
    const int* __restrict__ st, float* __restrict__ og, float* __restrict__ lgg)
{
    extern __shared__ float sm[];
    float* r     = sm;                  // 128 x RS   raw qk rows (q + keys)
    float* vv    = r + 128 * RS;        // 128 x 64   v rows
    float* dots  = vv + 128 * 64;       // 64 x DS
    float* inorm = dots + 64 * DS;      // 128
    float* logit = inorm + 128;         // 64
    int*   kpos  = (int*)(logit + 64);  // 128
    int*   qh    = kpos + 128;          // 64

    int tid = threadIdx.x;
    int bh = blockIdx.x >> 8, c = blockIdx.x & 255;
    int cp = (c + NCH - 1) & 255;

    {
        int lc = (tid < 64) ? c : cp;
        int tk = st[(size_t)bh * NHT + lc * 64 + (tid & 63)];
        kpos[tid] = tk & (T_ - 1);
        if (tid < 64) qh[tid] = tk >> 11;
    }
    __syncthreads();

    const float* qb = qk + ((size_t)bh << 17);
    const float* vb = vg + ((size_t)bh << 17);
    for (int it = 0; it < 64; it++) {
        int idx = it * 128 + tid;
        int jj = idx >> 6, d = idx & 63;
        int pos = kpos[jj];
        r[jj * RS + d]    = qb[(pos << 6) + d];
        vv[(jj << 6) + d] = vb[(pos << 6) + d];
    }
    __syncthreads();
    {
        float s = 0.f, cs = 0.f;
        #pragma unroll 8
        for (int d = 0; d < 64; d++) {
            float x = r[tid * RS + d];
            float p = x * x; KAHAN(s, cs, p);
        }
        inorm[tid] = 1.f / fmaxf(sqrtf(s + cs), 1e-12f);
    }
    __syncthreads();

    int tx = tid & 15, ty = tid >> 4;
    float acc[8][8], cmp[8][8];
    #pragma unroll
    for (int i = 0; i < 8; i++)
        #pragma unroll
        for (int m = 0; m < 8; m++) { acc[i][m] = 0.f; cmp[i][m] = 0.f; }

    for (int db = 0; db < 16; db++) {
        float kvb[4][8];
        #pragma unroll
        for (int dd = 0; dd < 4; dd++)
            #pragma unroll
            for (int m = 0; m < 8; m++)
                kvb[dd][m] = r[(tx + 16 * m) * RS + db * 4 + dd];
        #pragma unroll
        for (int i = 0; i < 8; i++) {
            float qv[4];
            #pragma unroll
            for (int dd = 0; dd < 4; dd++) qv[dd] = r[(ty * 8 + i) * RS + db * 4 + dd];
            float pb[8];
            #pragma unroll
            for (int m = 0; m < 8; m++) {
                float p = qv[0] * kvb[0][m];
                p = fmaf(qv[1], kvb[1][m], p);
                p = fmaf(qv[2], kvb[2][m], p);
                p = fmaf(qv[3], kvb[3][m], p);
                pb[m] = p;
            }
            #pragma unroll
            for (int m = 0; m < 8; m++) KAHAN(acc[i][m], cmp[i][m], pb[m]);
        }
    }
    #pragma unroll
    for (int i = 0; i < 8; i++) {
        int row = ty * 8 + i; int rp = kpos[row];
        #pragma unroll
        for (int m = 0; m < 8; m++) {
            int col = tx + 16 * m;
            float dv = (acc[i][m] + cmp[i][m]) * inorm[col] * 0.125f;
            if (rp == kpos[col]) dv = -5e4f;
            dots[row * DS + col] = dv;
        }
    }
    __syncthreads();

    if (tid < 64) {
        float mx = -1e30f;
        #pragma unroll 8
        for (int j2 = 0; j2 < 128; j2++) mx = fmaxf(mx, dots[tid * DS + j2]);
        float s = 0.f;
        #pragma unroll 8
        for (int j2 = 0; j2 < 128; j2++) s += expf(dots[tid * DS + j2] - mx);
        float lg = mx + logf(s);
        logit[tid] = lg;
        lgg[((size_t)bh * NH + qh[tid]) * T_ + kpos[tid]] = lg;
    }
    __syncthreads();
    for (int it = 0; it < 64; it++) {
        int idx = it * 128 + tid; int i = idx >> 7, j2 = idx & 127;
        dots[i * DS + j2] = expf(dots[i * DS + j2] - logit[i]);
    }
    __syncthreads();

    float a2[8][4], c2[8][4];
    #pragma unroll
    for (int i = 0; i < 8; i++)
        #pragma unroll
        for (int m = 0; m < 4; m++) { a2[i][m] = 0.f; c2[i][m] = 0.f; }
    for (int jb = 0; jb < 32; jb++) {
        float vwb[4][4];
        #pragma unroll
        for (int dd = 0; dd < 4; dd++)
            #pragma unroll
            for (int m = 0; m < 4; m++)
                vwb[dd][m] = vv[(((jb * 4 + dd)) << 6) + tx + 16 * m];
        #pragma unroll
        for (int i = 0; i < 8; i++) {
            float pv[4];
            #pragma unroll
            for (int dd = 0; dd < 4; dd++) pv[dd] = dots[(ty * 8 + i) * DS + jb * 4 + dd];
            float pb[4];
            #pragma unroll
            for (int m = 0; m < 4; m++) {
                float p = pv[0] * vwb[0][m];
                p = fmaf(pv[1], vwb[1][m], p);
                p = fmaf(pv[2], vwb[2][m], p);
                p = fmaf(pv[3], vwb[3][m], p);
                pb[m] = p;
            }
            #pragma unroll
            for (int m = 0; m < 4; m++) KAHAN(a2[i][m], c2[i][m], pb[m]);
        }
    }
    #pragma unroll
    for (int i = 0; i < 8; i++) {
        int row = ty * 8 + i;
        size_t base = (((size_t)bh * NH + qh[row]) * T_ + kpos[row]) << 6;
        #pragma unroll
        for (int m = 0; m < 4; m++) og[base + tx + 16 * m] = a2[i][m] + c2[i][m];
    }
}

// ------------------------- combine hash rounds ------------------------------
__global__ __launch_bounds__(64) void combine_kernel(
    const float* __restrict__ og, const float* __restrict__ lgg, float* __restrict__ at)
{
    __shared__ float w[8];
    int bh = blockIdx.x >> 11, pos = blockIdx.x & 2047;
    int tid = threadIdx.x;
    if (tid == 0) {
        float v[8]; float mx = -1e30f;
        #pragma unroll
        for (int h = 0; h < 8; h++) {
            v[h] = lgg[((size_t)bh * NH + h) * T_ + pos];
            mx = fmaxf(mx, v[h]);
        }
        float s = 0.f;
        #pragma unroll
        for (int h = 0; h < 8; h++) { v[h] = expf(v[h] - mx); s += v[h]; }
        float is = 1.f / s;
        #pragma unroll
        for (int h = 0; h < 8; h++) w[h] = v[h] * is;
    }
    __syncthreads();
    float acc = 0.f, cc = 0.f;
    #pragma unroll
    for (int h = 0; h < 8; h++) {
        float p = w[h] * og[(((size_t)bh * NH + h) * T_ + pos) * 64 + tid];
        KAHAN(acc, cc, p);
    }
    int b = bh >> 3, hd = bh & 7;
    at[((size_t)(b * T_ + pos)) * DIM + hd * 64 + tid] = acc + cc;
}

// ------------------------- frontend helpers ---------------------------------
__global__ void wt_kernel(const float* __restrict__ w, float* __restrict__ wT)
{
    int idx = blockIdx.x * 256 + threadIdx.x;     // KC*DIM
    int c = idx / DIM, o2 = idx - c * DIM;
    wT[idx] = (c < 687) ? w[(size_t)o2 * 687 + c] : 0.f;
}

__global__ void im2col_kernel(const float* __restrict__ spec, float* __restrict__ im)
{
    int idx = blockIdx.x * 256 + threadIdx.x;     // BT*KC
    int row = idx / KC, c = idx - row * KC;
    int b = row >> 11, t = row & 2047;
    float val = 0.f;
    if (c < 687) {
        int i = c / 3, k = c - i * 3;
        int tt = t + k - 1;
        if (tt >= 0 && tt < T_) val = spec[((size_t)b * T_ + tt) * 229 + i];
    }
    im[idx] = val;
}

__global__ void pe_kernel(float* __restrict__ x1, float* __restrict__ x2,
                          const float* __restrict__ per, const float* __restrict__ pec)
{
    int idx = blockIdx.x * 256 + threadIdx.x;     // BT*DIM
    int c = idx & 511;
    int t = (idx >> 9) & 2047;
    float p = (c < 256) ? per[(t >> 6) * 256 + c] : pec[(t & 63) * 256 + (c - 256)];
    float v = x1[idx] + p;
    x1[idx] = v; x2[idx] = v;
}

__global__ void avg_kernel(const float* __restrict__ a, const float* __restrict__ b,
                           float* __restrict__ y)
{
    int idx = blockIdx.x * 256 + threadIdx.x;
    y[idx] = 0.5f * (a[idx] + b[idx]);
}

// ------------------------- driver -------------------------------------------
extern "C" void kernel_launch(void* const* d_in, const int* in_sizes, int n_in,
                              void* d_out, int out_size)
{
    const float* spec   = (const float*)d_in[0];
    const float* conv_w = (const float*)d_in[1];
    const float* conv_b = (const float*)d_in[2];
    const float* pe_row = (const float*)d_in[3];
    const float* pe_col = (const float*)d_in[4];
    const float* lnA_g  = (const float*)d_in[5];
    const float* lnA_b  = (const float*)d_in[6];
    const float* wqk    = (const float*)d_in[7];
    const float* wv     = (const float*)d_in[8];
    const float* wo     = (const float*)d_in[9];
    const float* bo     = (const float*)d_in[10];
    const float* lnF_g  = (const float*)d_in[11];
    const float* lnF_b  = (const float*)d_in[12];
    const float* w1     = (const float*)d_in[13];
    const float* b1     = (const float*)d_in[14];
    const float* w2     = (const float*)d_in[15];
    const float* b2     = (const float*)d_in[16];
    const float* lin_w  = (const float*)d_in[17];
    const float* lin_b  = (const float*)d_in[18];
    const float* rot    = (const float*)d_in[19];
    float* out = (float*)d_out;

    float *x1, *x2, *tmp, *qk, *v, *at, *ff, *im, *wT, *o, *lg;
    int *bk, *st;
    cudaGetSymbolAddress((void**)&x1, g_x1);
    cudaGetSymbolAddress((void**)&x2, g_x2);
    cudaGetSymbolAddress((void**)&tmp, g_tmp);
    cudaGetSymbolAddress((void**)&qk, g_qk);
    cudaGetSymbolAddress((void**)&v,  g_v);
    cudaGetSymbolAddress((void**)&at, g_at);
    cudaGetSymbolAddress((void**)&ff, g_ffb);
    cudaGetSymbolAddress((void**)&im, g_im);
    cudaGetSymbolAddress((void**)&wT, g_wT);
    cudaGetSymbolAddress((void**)&o,  g_o);
    cudaGetSymbolAddress((void**)&lg, g_lg);
    cudaGetSymbolAddress((void**)&bk, g_bk);
    cudaGetSymbolAddress((void**)&st, g_st);

    size_t asmem = (size_t)(128 * RS + 128 * 64 + 64 * DS + 128 + 64 + 128 + 64) * 4;
    cudaFuncSetAttribute(attn_kernel, cudaFuncAttributeMaxDynamicSharedMemorySize, (int)asmem);

    // frontend: conv1d (im2col GEMM) + relu + axial positional embedding
    wt_kernel<<<(KC * DIM) / 256, 256>>>(conv_w, wT);
    im2col_kernel<<<(BT * KC) / 256, 256>>>(spec, im);
    sgemm<<<dim3(DIM / 64, BT / 64), 256>>>(im, wT, conv_b, nullptr, x1,
                                            BT, DIM, KC, 1, 0, nullptr, nullptr, 0);
    pe_kernel<<<(BT * DIM) / 256, 256>>>(x1, x2, pe_row, pe_col);

    for (int i = 0; i < 8; i++) {
        ln_kernel<<<BT, 256>>>(x2, lnA_g + i * DIM, lnA_b + i * DIM, tmp);
        // fused QK + V projection (heads layout), 1024 CTAs
        sgemm<<<dim3(16, 64), 256>>>(tmp, wqk + (size_t)i * DIM * DIM, nullptr, nullptr,
                                     qk, BT, DIM, DIM, 0, 1,
                                     wv + (size_t)i * DIM * DIM, v, DIM);
        hash_kernel<<<BH * (T_ / TCH), 128>>>(qk, rot + (size_t)i * 64 * 128, bk);
        sort_kernel<<<BH, 256>>>(bk, st);
        attn_kernel<<<BH * NCH, 128, asmem>>>(qk, v, st, o, lg);
        combine_kernel<<<BH * T_, 64>>>(o, lg, at);
        sgemm<<<dim3(8, 64), 256>>>(at, wo + (size_t)i * DIM * DIM, bo + i * DIM,
                                    x1, x1, BT, DIM, DIM, 0, 0, nullptr, nullptr, 0);
        ln_kernel<<<BT, 256>>>(x1, lnF_g + i * DIM, lnF_b + i * DIM, tmp);
        sgemm<<<dim3(FF / 64, 64), 256>>>(tmp, w1 + (size_t)i * DIM * FF, b1 + i * FF,
                                          nullptr, ff, BT, FF, DIM, 2, 0, nullptr, nullptr, 0);
        sgemm<<<dim3(8, 64), 256>>>(ff, w2 + (size_t)i * DIM * FF, b2 + i * DIM,
                                    x2, x2, BT, DIM, FF, 0, 0, nullptr, nullptr, 0);
    }

    avg_kernel<<<(BT * DIM) / 256, 256>>>(x1, x2, tmp);
    sgemm<<<dim3(2, 64), 256>>>(tmp, lin_w, lin_b, nullptr, out, BT, 88, DIM, 0, 0,
                                nullptr, nullptr, 0);
}